// round 16
// baseline (speedup 1.0000x reference)
#include <cuda_runtime.h>
#include <cuda_fp16.h>
#include <math.h>
#include <stdint.h>

// x[131072,256] @ W1[256,512] -> tanh -> @W2[512,512] -> tanh -> @W3[512,128] (+biases).
// Fixed-point loop converges to F(x) within ~4e-7 abs => output == MLP forward.
// Numerics (twice-calibrated): single-fp16 A and B, fp32 accum -> 5.045e-4.
// R16 = R13 (best, 474us) + L1 reads x fp32 directly (in-kernel cvt), killing the
// serialized prep-x pass. Same rounding path -> bit-identical output.
constexpr int BATCH = 131072;
constexpr int DIN   = 256;
constexpr int HID   = 512;
constexpr int DOUT  = 128;

// ---------- device scratch (static; no runtime allocation allowed) ----------
__device__ __align__(256) __half g_h1[(size_t)BATCH * HID];
__device__ __align__(256) __half g_h2[(size_t)BATCH * HID];

constexpr size_t W1_OFF = 0;
constexpr size_t W1_SZ  = (size_t)HID * DIN;
constexpr size_t W2_OFF = W1_OFF + W1_SZ;
constexpr size_t W2_SZ  = (size_t)HID * HID;
constexpr size_t W3_OFF = W2_OFF + W2_SZ;
constexpr size_t W3_SZ  = (size_t)DOUT * HID;
__device__ __align__(256) __half g_w[W1_SZ + W2_SZ + W3_SZ];   // fp16 weights, [N,K] K-major

// ---------- PTX helpers (compute_103-safe: NO tcgen05) ----------
__device__ __forceinline__ uint32_t smem_u32(const void* p) {
    uint32_t a;
    asm("{ .reg .u64 t; cvta.to.shared.u64 t, %1; cvt.u32.u64 %0, t; }" : "=r"(a) : "l"(p));
    return a;
}
__device__ __forceinline__ void cp16(uint32_t dst, const void* src) {
    asm volatile("cp.async.cg.shared.global [%0], [%1], 16;" :: "r"(dst), "l"(src));
}
__device__ __forceinline__ void cp_commit() { asm volatile("cp.async.commit_group;"); }
__device__ __forceinline__ void cp_wait1()  { asm volatile("cp.async.wait_group 1;"); }

__device__ __forceinline__ void ldsm4(uint32_t* r, uint32_t addr) {
    asm volatile("ldmatrix.sync.aligned.m8n8.x4.shared.b16 {%0,%1,%2,%3}, [%4];"
                 : "=r"(r[0]), "=r"(r[1]), "=r"(r[2]), "=r"(r[3]) : "r"(addr));
}
__device__ __forceinline__ void mma16816(float* d, const uint32_t* a, const uint32_t* b) {
    asm volatile("mma.sync.aligned.m16n8k16.row.col.f32.f16.f16.f32 "
                 "{%0,%1,%2,%3}, {%4,%5,%6,%7}, {%8,%9}, {%0,%1,%2,%3};"
                 : "+f"(d[0]), "+f"(d[1]), "+f"(d[2]), "+f"(d[3])
                 : "r"(a[0]), "r"(a[1]), "r"(a[2]), "r"(a[3]), "r"(b[0]), "r"(b[1]));
}

// fast accurate tanh: (e-1)/(e+1), e = 2^(2x*log2e). abs err ~1e-7.
__device__ __forceinline__ float tanh_fast(float x) {
    float xc = fminf(fmaxf(x, -15.0f), 15.0f);
    float e;
    asm("ex2.approx.f32 %0, %1;" : "=f"(e) : "f"(xc * 2.885390081777927f));
    float r;
    asm("rcp.approx.f32 %0, %1;" : "=f"(r) : "f"(e + 1.0f));
    return (e - 1.0f) * r;
}

__device__ __forceinline__ uint32_t pack2h(float v0, float v1) {
    __half h0 = __float2half_rn(v0);
    __half h1 = __float2half_rn(v1);
    return (uint32_t)__half_as_ushort(h0) | ((uint32_t)__half_as_ushort(h1) << 16);
}

// ---------- prep: weights only (x conversion is fused into the L1 GEMM) ----------
constexpr int WTOT = (int)(W1_SZ + W2_SZ + W3_SZ);                // 458752
constexpr int WB = (WTOT + 255) / 256;                            // 1792

__global__ void prep_w(const float* __restrict__ W1,
                       const float* __restrict__ W2,
                       const float* __restrict__ W3)
{
    int idx = blockIdx.x * 256 + threadIdx.x;
    if (idx >= WTOT) return;
    const float* W; int K, N, loc;
    if (idx < (int)W2_OFF)      { W = W1; K = DIN; N = HID;  loc = idx; }
    else if (idx < (int)W3_OFF) { W = W2; K = HID; N = HID;  loc = idx - (int)W2_OFF; }
    else                        { W = W3; K = HID; N = DOUT; loc = idx - (int)W3_OFF; }
    int n = loc / K;
    int k = loc - n * K;
    g_w[idx] = __float2half_rn(W[(size_t)k * N + n]);
}

// ---------- main GEMM: 128x128 tile, BK=32, 3-stage cp.async, single sync/iter ----------
// Normal path (AFP32=false): A fp16 via cp.async, layout as R13 (best kernel).
// AFP32 path (L1 only): A read as fp32 from x via LDG->cvt->STS, one-chunk register
// prefetch, 2 alternating A buffers living in stage-slots 0/1's A regions.
constexpr uint32_t OFF_A = 0;
constexpr uint32_t OFF_B = 8192;
constexpr uint32_t STAGE = 16384;
constexpr int SMEM_TOTAL = 3 * STAGE;   // 48KB -> 2 CTAs/SM (reg-limited)

template<bool TANH, bool FP32OUT, bool AFP32>
__global__ __launch_bounds__(256, 2)
void gemm_hmma(const float* __restrict__ Xf, int aSel, size_t wOff,
               const float* __restrict__ bias,
               int cSel, float* __restrict__ Cf, int N, int K)
{
    const __half* A = (aSel == 1) ? g_h1 : g_h2;     // unused when AFP32
    __half* C = (cSel == 1) ? g_h1 : (cSel == 2) ? g_h2 : nullptr;
    const __half* W = g_w + wOff;

    extern __shared__ char smem[];
    const uint32_t sbase = smem_u32(smem);
    const int tid  = threadIdx.x;
    const int wid  = tid >> 5;
    const int lane = tid & 31;
    const int mBase = blockIdx.y * 128;
    const int nBase = blockIdx.x * 128;
    const int warpM = (wid >> 1) * 32;
    const int warpN = (wid & 1) * 64;
    const int NC = K / 32;

    // ---- fp16 loader mapping (A when !AFP32, B always) ----
    const int lr = tid >> 2;               // 0..63
    const int lj = tid & 3;
    const uint32_t swj = (uint32_t)lj * 16;
    auto so = [&](uint32_t row) { return row * 64 + (swj ^ ((row & 6) << 3)); };
    const uint32_t soA0 = so((uint32_t)lr), soA1 = so((uint32_t)(lr + 64));
    const size_t jcol = (size_t)lj * 8;
    const size_t gA0 = (size_t)(mBase + lr) * K + jcol;
    const size_t gA1 = (size_t)(mBase + lr + 64) * K + jcol;
    const size_t gB0 = (size_t)(nBase + lr) * K + jcol;
    const size_t gB1 = (size_t)(nBase + lr + 64) * K + jcol;

    auto loadChunk = [&](int kc, int s) {
        const uint32_t sb = sbase + (uint32_t)s * STAGE;
        const size_t co = (size_t)kc * 32;
        if (!AFP32) {
            cp16(sb + OFF_A + soA0, A + gA0 + co);
            cp16(sb + OFF_A + soA1, A + gA1 + co);
        }
        cp16(sb + OFF_B + soA0, W + gB0 + co);
        cp16(sb + OFF_B + soA1, W + gB1 + co);
    };

    // ---- AFP32: A tile loader (128 rows x 32 fp32 cols; 16 floats/thread) ----
    const int xrow = tid >> 1;                       // 0..127
    const int xhalf = tid & 1;                       // 16-float segment
    const float* xptr = AFP32
        ? (Xf + (size_t)(mBase + xrow) * K + xhalf * 16) : nullptr;
    float4 xr[4];
    auto ldgA = [&](int kc) {
        const float* p = xptr + (size_t)kc * 32;
        xr[0] = *reinterpret_cast<const float4*>(p);
        xr[1] = *reinterpret_cast<const float4*>(p + 4);
        xr[2] = *reinterpret_cast<const float4*>(p + 8);
        xr[3] = *reinterpret_cast<const float4*>(p + 12);
    };
    auto stsA = [&](int buf) {
        const uint32_t row = (uint32_t)xrow;
        const uint32_t base = sbase + (uint32_t)buf * STAGE + OFF_A + row * 64;
        const uint32_t sw = (row & 6) << 3;
        const uint32_t j0 = (uint32_t)xhalf * 2;
        uint4 o0, o1;
        o0.x = pack2h(xr[0].x, xr[0].y); o0.y = pack2h(xr[0].z, xr[0].w);
        o0.z = pack2h(xr[1].x, xr[1].y); o0.w = pack2h(xr[1].z, xr[1].w);
        o1.x = pack2h(xr[2].x, xr[2].y); o1.y = pack2h(xr[2].z, xr[2].w);
        o1.z = pack2h(xr[3].x, xr[3].y); o1.w = pack2h(xr[3].z, xr[3].w);
        *reinterpret_cast<uint4*>(smem + (base + ((j0 * 16) ^ sw) - sbase))       = o0;
        *reinterpret_cast<uint4*>(smem + (base + (((j0 + 1) * 16) ^ sw) - sbase)) = o1;
    };

    float acc[2][8][4];
    #pragma unroll
    for (int i = 0; i < 2; i++)
        #pragma unroll
        for (int j = 0; j < 8; j++)
            #pragma unroll
            for (int q = 0; q < 4; q++) acc[i][j][q] = 0.0f;

    const int lrow = lane & 15, lhi = lane >> 4;

    // hoisted fragment smem-offset components
    uint32_t aRow[2], aSw[2], bRow[4], bSw[4];
    #pragma unroll
    for (int i = 0; i < 2; i++) {
        uint32_t row = warpM + i * 16 + lrow;
        aRow[i] = row * 64; aSw[i] = (row & 6) << 3;
    }
    #pragma unroll
    for (int p = 0; p < 4; p++) {
        uint32_t row = warpN + p * 16 + lrow;
        bRow[p] = row * 64; bSw[p] = (row & 6) << 3;
    }

    if (AFP32) ldgA(0);
    loadChunk(0, 0); cp_commit();
    loadChunk(1, 1); cp_commit();

    for (int c = 0; c < NC; c++) {
        cp_wait1();
        if (AFP32) {
            stsA(c & 1);                        // stage A chunk c (regs -> smem)
            if (c + 1 < NC) ldgA(c + 1);        // prefetch next chunk into regs
        }
        __syncthreads();
        if (c + 2 < NC) loadChunk(c + 2, (c + 2) % 3);
        cp_commit();

        const uint32_t sbB = sbase + (uint32_t)(c % 3) * STAGE;
        const uint32_t sbA = AFP32 ? (sbase + (uint32_t)(c & 1) * STAGE) : sbB;
        #pragma unroll
        for (int ks = 0; ks < 2; ks++) {
            const uint32_t colb = ks * 32 + lhi * 16;
            uint32_t ah[2][4], bb[8][2];
            #pragma unroll
            for (int i = 0; i < 2; i++) {
                uint32_t off = aRow[i] + (colb ^ aSw[i]);
                ldsm4(ah[i], sbA + OFF_A + off);
            }
            #pragma unroll
            for (int p = 0; p < 4; p++) {
                uint32_t off = bRow[p] + (colb ^ bSw[p]);
                uint32_t r[4];
                ldsm4(r, sbB + OFF_B + off);
                bb[2 * p][0] = r[0]; bb[2 * p][1] = r[2];
                bb[2 * p + 1][0] = r[1]; bb[2 * p + 1][1] = r[3];
            }
            #pragma unroll
            for (int i = 0; i < 2; i++)
                #pragma unroll
                for (int j = 0; j < 8; j++) mma16816(acc[i][j], ah[i], bb[j]);
        }
    }

    // ---------- epilogue ----------
    #pragma unroll
    for (int i = 0; i < 2; i++) {
        const int m0 = mBase + warpM + i * 16 + (lane >> 2);
        #pragma unroll
        for (int j = 0; j < 8; j++) {
            const int n = nBase + warpN + j * 8 + (lane & 3) * 2;
            const float2 bb2 = *reinterpret_cast<const float2*>(&bias[n]);
            float v00 = acc[i][j][0] + bb2.x, v01 = acc[i][j][1] + bb2.y;
            float v10 = acc[i][j][2] + bb2.x, v11 = acc[i][j][3] + bb2.y;
            if (TANH) {
                v00 = tanh_fast(v00); v01 = tanh_fast(v01);
                v10 = tanh_fast(v10); v11 = tanh_fast(v11);
            }
            if (FP32OUT) {
                *reinterpret_cast<float2*>(&Cf[(size_t)m0 * N + n])       = make_float2(v00, v01);
                *reinterpret_cast<float2*>(&Cf[(size_t)(m0 + 8) * N + n]) = make_float2(v10, v11);
            } else {
                *reinterpret_cast<uint32_t*>(&C[(size_t)m0 * N + n])       = pack2h(v00, v01);
                *reinterpret_cast<uint32_t*>(&C[(size_t)(m0 + 8) * N + n]) = pack2h(v10, v11);
            }
        }
    }
}

// ---------- launch ----------
extern "C" void kernel_launch(void* const* d_in, const int* in_sizes, int n_in,
                              void* d_out, int out_size)
{
    const float* x  = (const float*)d_in[0];
    const float* W1 = (const float*)d_in[1];
    const float* b1 = (const float*)d_in[2];
    const float* W2 = (const float*)d_in[3];
    const float* b2 = (const float*)d_in[4];
    const float* W3 = (const float*)d_in[5];
    const float* b3 = (const float*)d_in[6];
    float* out = (float*)d_out;

    prep_w<<<WB, 256>>>(W1, W2, W3);

    cudaFuncSetAttribute(gemm_hmma<true,  false, true >,
                         cudaFuncAttributeMaxDynamicSharedMemorySize, SMEM_TOTAL);
    cudaFuncSetAttribute(gemm_hmma<true,  false, false>,
                         cudaFuncAttributeMaxDynamicSharedMemorySize, SMEM_TOTAL);
    cudaFuncSetAttribute(gemm_hmma<false, true,  false>,
                         cudaFuncAttributeMaxDynamicSharedMemorySize, SMEM_TOTAL);

    dim3 grid12(HID / 128, BATCH / 128);   // (4, 1024)
    dim3 grid3 (DOUT / 128, BATCH / 128);  // (1, 1024)

    // L1: h1 = tanh(x(fp32) @ W1 + b1)   — fused x conversion
    gemm_hmma<true,  false, true ><<<grid12, 256, SMEM_TOTAL>>>(x, 0, W1_OFF, b1, 1, nullptr, HID, DIN);
    // L2: h2 = tanh(h1 @ W2 + b2)
    gemm_hmma<true,  false, false><<<grid12, 256, SMEM_TOTAL>>>(nullptr, 1, W2_OFF, b2, 2, nullptr, HID, HID);
    // L3: out = h2 @ W3 + b3
    gemm_hmma<false, true,  false><<<grid3,  256, SMEM_TOTAL>>>(nullptr, 2, W3_OFF, b3, 0, out, DOUT, HID);
}